// round 8
// baseline (speedup 1.0000x reference)
#include <cuda_runtime.h>
#include <cstdint>

#define U        128
#define G4       512
#define SKIPN    16
#define TSTEPS   128
#define BATCH    64
#define FLATN    16384   // SEQ * UNITS

// Scratch (device globals: allocation-free rule)
__device__ float g_xpe[8192 * 512];      // encoder input projections, row = t*64+b
__device__ float g_flat[BATCH * FLATN];  // decoder outputs (dense GEMM A-matrix)

// ---------------- f32x2 helpers (sm_103a packed fp32) ----------------
__device__ __forceinline__ void fma2(unsigned long long &d, unsigned long long a, unsigned long long b) {
    asm("fma.rn.f32x2 %0, %1, %2, %0;" : "+l"(d) : "l"(a), "l"(b));
}
__device__ __forceinline__ unsigned long long pack2(float lo, float hi) {
    unsigned long long r;
    asm("mov.b64 %0, {%1, %2};" : "=l"(r) : "f"(lo), "f"(hi));
    return r;
}
__device__ __forceinline__ void unpack2(float &lo, float &hi, unsigned long long v) {
    asm("mov.b64 {%0, %1}, %2;" : "=f"(lo), "=f"(hi) : "l"(v));
}

__device__ __forceinline__ float sigm(float x) { return 1.0f / (1.0f + expf(-x)); }

// ================= Kernel 1: encoder input projection =================
// XPe[t*64+b][g] = X[b,0,t,:] @ enc_kernel[:,g] + enc_bias[g]
// 512 blocks x 128 threads; block = 16 rows x 512 cols; thread = 16 rows x 4 cols
__global__ __launch_bounds__(128) void k_xproj(const float* __restrict__ X,
                                               const float* __restrict__ Wk,
                                               const float* __restrict__ bias) {
    __shared__ float As[128 * 16];   // [k][r] transposed
    const int tid  = threadIdx.x;
    const int row0 = blockIdx.x * 16;

    for (int idx = tid; idx < 16 * 128; idx += 128) {
        int r = idx >> 7, m = idx & 127;
        int row = row0 + r;
        int t = row >> 6, b = row & 63;
        As[m * 16 + r] = X[(size_t)b * 32768 + t * 128 + m];
    }
    __syncthreads();

    const int c0 = tid * 4;
    float4 bs = *(const float4*)(bias + c0);
    float acc[16][4];
#pragma unroll
    for (int r = 0; r < 16; r++) { acc[r][0] = bs.x; acc[r][1] = bs.y; acc[r][2] = bs.z; acc[r][3] = bs.w; }

#pragma unroll 4
    for (int k = 0; k < 128; k++) {
        float4 w = *(const float4*)(Wk + k * 512 + c0);
#pragma unroll
        for (int r = 0; r < 16; r++) {
            float a = As[k * 16 + r];
            acc[r][0] = fmaf(a, w.x, acc[r][0]);
            acc[r][1] = fmaf(a, w.y, acc[r][1]);
            acc[r][2] = fmaf(a, w.z, acc[r][2]);
            acc[r][3] = fmaf(a, w.w, acc[r][3]);
        }
    }
#pragma unroll
    for (int r = 0; r < 16; r++) {
        float4 o; o.x = acc[r][0]; o.y = acc[r][1]; o.z = acc[r][2]; o.w = acc[r][3];
        *(float4*)(g_xpe + (size_t)(row0 + r) * 512 + c0) = o;
    }
}

// ================= Kernel 2: fused skip-LSTM recurrence =================
// One CTA per batch element (64 CTAs x 320 threads).
// Threads 0..255: the 512 gate pre-activations (2 each, float2 weights)
// Threads 256..319: the 128 skip pre-activations (2 each)
// Threads 0..127: elementwise gate update / state rotation.
__device__ __forceinline__ void lstm_step(
    int tid, int t, const float* xp, const float* __restrict__ rk,
    const float* __restrict__ k2w, const float* __restrict__ bias2,
    float s0, float* sg, float* sc, float* ph, float* spre, float* sh,
    float* out_h) {
    if (tid < 256) {
        const int j0 = tid * 2;
        const int q  = j0 >> 7;
        const float* w = rk + j0;
        const float* s = sg + (q << 7);
        float a0 = xp[j0], a1 = xp[j0 + 1];
#pragma unroll 4
        for (int k = 0; k < 128; k++) {
            float2 wv = *(const float2*)(w + k * 512);
            float sv = s[k];
            a0 = fmaf(sv, wv.x, a0);
            a1 = fmaf(sv, wv.y, a1);
        }
        spre[j0] = a0; spre[j0 + 1] = a1;
    } else {
        const int j0 = (tid - 256) * 2;
        const float* hold = ph + ((t & (SKIPN - 1)) << 7);  // oldest h in ring
        float a0 = bias2[j0], a1 = bias2[j0 + 1];
#pragma unroll 4
        for (int k = 0; k < 128; k++) {
            float2 wv = *(const float2*)(k2w + k * 128 + j0);
            float sv = hold[k];
            a0 = fmaf(sv, wv.x, a0);
            a1 = fmaf(sv, wv.y, a1);
        }
        spre[512 + j0] = a0; spre[512 + j0 + 1] = a1;
    }
    __syncthreads();
    if (tid < 128) {
        const int j = tid;
        float gi = sigm(spre[j]);
        float gf = sigm(spre[128 + j]);
        float cb = tanhf(spre[256 + j]);
        float go = sigm(spre[384 + j]);
        float c  = gf * sc[j] + gi * cb;
        float hs = sigm(spre[512 + j]);
        float h  = s0 * (go * tanhf(c)) + (1.0f - s0) * hs;
        // next step's recurrent input is concat(i, f, c_new, o)
        sg[j] = gi; sg[128 + j] = gf; sg[256 + j] = c; sg[384 + j] = go;
        sc[j] = c;
        ph[((t & (SKIPN - 1)) << 7) + j] = h;   // rotate ring (oldest slot consumed above)
        sh[j] = h;
        if (out_h) out_h[j] = h;
    }
    __syncthreads();
}

__global__ __launch_bounds__(320) void k_lstm(
    const float* __restrict__ enc_rk, const float* __restrict__ enc_k2,
    const float* __restrict__ enc_b2, const float* __restrict__ enc_s0p,
    const float* __restrict__ dec_k,  const float* __restrict__ dec_rk,
    const float* __restrict__ dec_k2, const float* __restrict__ dec_b,
    const float* __restrict__ dec_b2, const float* __restrict__ dec_s0p) {
    __shared__ __align__(16) float sg[512];
    __shared__ __align__(16) float sc[128];
    __shared__ __align__(16) float sh[128];
    __shared__ __align__(16) float ph[SKIPN * 128];
    __shared__ __align__(16) float spre[640];
    __shared__ __align__(16) float xpd[512];

    const int tid = threadIdx.x;
    const int b   = blockIdx.x;

    for (int i = tid; i < 512; i += 320) sg[i] = 0.f;
    for (int i = tid; i < 128; i += 320) sc[i] = 0.f;
    for (int i = tid; i < SKIPN * 128; i += 320) ph[i] = 0.f;
    __syncthreads();

    // ---------- encoder ----------
    const float s0e = *enc_s0p;
    for (int t = 0; t < TSTEPS; t++) {
        const float* xp = g_xpe + ((size_t)t * 64 + b) * 512;
        lstm_step(tid, t, xp, enc_rk, enc_k2, enc_b2, s0e, sg, sc, ph, spre, sh, nullptr);
    }
    // sh now holds RE[b]

    // ---------- decoder constant input projection: xpd = dec_bias + RE @ dec_kernel ----------
    if (tid < 256) {
        const int j0 = tid * 2;
        float a0 = dec_b[j0], a1 = dec_b[j0 + 1];
#pragma unroll 4
        for (int k = 0; k < 128; k++) {
            float2 wv = *(const float2*)(dec_k + k * 512 + j0);
            float sv = sh[k];
            a0 = fmaf(sv, wv.x, a0);
            a1 = fmaf(sv, wv.y, a1);
        }
        xpd[j0] = a0; xpd[j0 + 1] = a1;
    }
    // re-zero state (separate arrays from sh/xpd; race-free)
    for (int i = tid; i < 512; i += 320) sg[i] = 0.f;
    for (int i = tid; i < 128; i += 320) sc[i] = 0.f;
    for (int i = tid; i < SKIPN * 128; i += 320) ph[i] = 0.f;
    __syncthreads();

    // ---------- decoder ----------
    const float s0d = *dec_s0p;
    for (int t = 0; t < TSTEPS; t++) {
        lstm_step(tid, t, xpd, dec_rk, dec_k2, dec_b2, s0d, sg, sc, ph, spre, sh,
                  g_flat + (size_t)b * FLATN + t * 128);
    }
}

// ================= Kernel 3: dense output layer (f32x2) =================
// Y[b,j] = dense_b[j] + sum_k flat[b,k] * W[j,k]
// 128 CTAs (j tiles of 128) x 128 threads; CTA tile 64b x 128j; thread tile 8b x 8j.
// Accumulators are f32x2 pairs over adjacent b (FFMA2 = 2x fp32 rate).
__global__ __launch_bounds__(128, 1) void k_dense(const float* __restrict__ W,
                                                  const float* __restrict__ bias,
                                                  float* __restrict__ out) {
    __shared__ __align__(16) float As[32 * 68];   // [k][b], padded stride 68
    __shared__ __align__(16) float Bs[32 * 132];  // [k][j], padded stride 132

    const int tid = threadIdx.x;
    const int j0  = blockIdx.x * 128;
    const int jg  = tid & 15, bg = tid >> 4;
    const int jt0 = jg * 8,   b0 = bg * 8;

    unsigned long long acc[8][4];
#pragma unroll
    for (int jj = 0; jj < 8; jj++) {
        float bz = bias[j0 + jt0 + jj];
        unsigned long long p = pack2(bz, bz);
        acc[jj][0] = p; acc[jj][1] = p; acc[jj][2] = p; acc[jj][3] = p;
    }

    // staging: A — two threads per b row cover 32 k; B — one thread per j row
    const int bA = tid >> 1;
    const int hk = (tid & 1) * 16;
    const float* Aptr = g_flat + (size_t)bA * FLATN + hk;
    const float* Bptr = W + (size_t)(j0 + tid) * FLATN;

    float4 rA[4], rB[8];
#pragma unroll
    for (int i = 0; i < 4; i++) rA[i] = *(const float4*)(Aptr + i * 4);
#pragma unroll
    for (int i = 0; i < 8; i++) rB[i] = *(const float4*)(Bptr + i * 4);

    for (int c = 0; c < 512; c++) {
        __syncthreads();
        // commit staged chunk c to SMEM
#pragma unroll
        for (int i = 0; i < 4; i++) {
            int k = hk + i * 4;
            As[(k + 0) * 68 + bA] = rA[i].x;
            As[(k + 1) * 68 + bA] = rA[i].y;
            As[(k + 2) * 68 + bA] = rA[i].z;
            As[(k + 3) * 68 + bA] = rA[i].w;
        }
#pragma unroll
        for (int i = 0; i < 8; i++) {
            int k = i * 4;
            Bs[(k + 0) * 132 + tid] = rB[i].x;
            Bs[(k + 1) * 132 + tid] = rB[i].y;
            Bs[(k + 2) * 132 + tid] = rB[i].z;
            Bs[(k + 3) * 132 + tid] = rB[i].w;
        }
        __syncthreads();

        // prefetch chunk c+1 (overlaps with compute below)
        if (c + 1 < 512) {
            const float* ap = Aptr + (size_t)(c + 1) * 32;
            const float* bp = Bptr + (size_t)(c + 1) * 32;
#pragma unroll
            for (int i = 0; i < 4; i++) rA[i] = *(const float4*)(ap + i * 4);
#pragma unroll
            for (int i = 0; i < 8; i++) rB[i] = *(const float4*)(bp + i * 4);
        }

#pragma unroll 4
        for (int k = 0; k < 32; k++) {
            ulonglong2 a01 = *(const ulonglong2*)(As + k * 68 + b0);
            ulonglong2 a23 = *(const ulonglong2*)(As + k * 68 + b0 + 4);
            float4 bv0 = *(const float4*)(Bs + k * 132 + jt0);
            float4 bv1 = *(const float4*)(Bs + k * 132 + jt0 + 4);
            float bvs[8] = {bv0.x, bv0.y, bv0.z, bv0.w, bv1.x, bv1.y, bv1.z, bv1.w};
#pragma unroll
            for (int jj = 0; jj < 8; jj++) {
                unsigned long long bb = pack2(bvs[jj], bvs[jj]);
                fma2(acc[jj][0], a01.x, bb);
                fma2(acc[jj][1], a01.y, bb);
                fma2(acc[jj][2], a23.x, bb);
                fma2(acc[jj][3], a23.y, bb);
            }
        }
    }

    // epilogue
#pragma unroll
    for (int jj = 0; jj < 8; jj++) {
        int j = j0 + jt0 + jj;
#pragma unroll
        for (int p = 0; p < 4; p++) {
            float lo, hi;
            unpack2(lo, hi, acc[jj][p]);
            int bb = b0 + 2 * p;
            out[(size_t)bb * FLATN + j]       = lo;
            out[(size_t)(bb + 1) * FLATN + j] = hi;
        }
    }
}

// ================= launch =================
extern "C" void kernel_launch(void* const* d_in, const int* in_sizes, int n_in,
                              void* d_out, int out_size) {
    const float* X      = (const float*)d_in[0];
    const float* enc_k  = (const float*)d_in[1];
    const float* enc_rk = (const float*)d_in[2];
    const float* enc_k2 = (const float*)d_in[3];
    const float* enc_b  = (const float*)d_in[4];
    const float* enc_b2 = (const float*)d_in[5];
    const float* enc_s0 = (const float*)d_in[6];
    const float* dec_k  = (const float*)d_in[7];
    const float* dec_rk = (const float*)d_in[8];
    const float* dec_k2 = (const float*)d_in[9];
    const float* dec_b  = (const float*)d_in[10];
    const float* dec_b2 = (const float*)d_in[11];
    const float* dec_s0 = (const float*)d_in[12];
    const float* dw     = (const float*)d_in[13];
    const float* db     = (const float*)d_in[14];
    float* out = (float*)d_out;

    k_xproj<<<512, 128>>>(X, enc_k, enc_b);
    k_lstm<<<64, 320>>>(enc_rk, enc_k2, enc_b2, enc_s0,
                        dec_k, dec_rk, dec_k2, dec_b, dec_b2, dec_s0);
    k_dense<<<128, 128>>>(dw, db, out);
}

// round 10
// speedup vs baseline: 1.2511x; 1.2511x over previous
#include <cuda_runtime.h>
#include <cstdint>

#define U        128
#define G4       512
#define SKIPN    16
#define TSTEPS   128
#define BATCH    64
#define FLATN    16384   // SEQ * UNITS

// Scratch (device globals: allocation-free rule)
__device__ float g_xpe[8192 * 512];      // encoder input projections, row = t*64+b
__device__ float g_flat[BATCH * FLATN];  // decoder outputs (dense GEMM B-matrix)

__device__ __forceinline__ float sigm(float x) { return 1.0f / (1.0f + expf(-x)); }

__device__ __forceinline__ uint32_t smem_u32(const void* p) {
    uint32_t a;
    asm("{ .reg .u64 t; cvta.to.shared.u64 t, %1; cvt.u32.u64 %0, t; }" : "=r"(a) : "l"(p));
    return a;
}
__device__ __forceinline__ void cp16(uint32_t dst, const float* src) {
    asm volatile("cp.async.cg.shared.global [%0], [%1], 16;" :: "r"(dst), "l"(src));
}
__device__ __forceinline__ uint32_t f2tf32(float f) {
    uint32_t r;
    asm("cvt.rna.tf32.f32 %0, %1;" : "=r"(r) : "f"(f));
    return r;
}
__device__ __forceinline__ void mma16n8k8(float* c, const uint32_t* a, uint32_t b0, uint32_t b1) {
    asm volatile(
        "mma.sync.aligned.m16n8k8.row.col.f32.tf32.tf32.f32 "
        "{%0,%1,%2,%3}, {%4,%5,%6,%7}, {%8,%9}, {%0,%1,%2,%3};"
        : "+f"(c[0]), "+f"(c[1]), "+f"(c[2]), "+f"(c[3])
        : "r"(a[0]), "r"(a[1]), "r"(a[2]), "r"(a[3]), "r"(b0), "r"(b1));
}

// ================= Kernel 1: encoder input projection =================
__global__ __launch_bounds__(128) void k_xproj(const float* __restrict__ X,
                                               const float* __restrict__ Wk,
                                               const float* __restrict__ bias) {
    __shared__ float As[128 * 16];   // [k][r] transposed
    const int tid  = threadIdx.x;
    const int row0 = blockIdx.x * 16;

    for (int idx = tid; idx < 16 * 128; idx += 128) {
        int r = idx >> 7, m = idx & 127;
        int row = row0 + r;
        int t = row >> 6, b = row & 63;
        As[m * 16 + r] = X[(size_t)b * 32768 + t * 128 + m];
    }
    __syncthreads();

    const int c0 = tid * 4;
    float4 bs = *(const float4*)(bias + c0);
    float acc[16][4];
#pragma unroll
    for (int r = 0; r < 16; r++) { acc[r][0] = bs.x; acc[r][1] = bs.y; acc[r][2] = bs.z; acc[r][3] = bs.w; }

#pragma unroll 4
    for (int k = 0; k < 128; k++) {
        float4 w = *(const float4*)(Wk + k * 512 + c0);
#pragma unroll
        for (int r = 0; r < 16; r++) {
            float a = As[k * 16 + r];
            acc[r][0] = fmaf(a, w.x, acc[r][0]);
            acc[r][1] = fmaf(a, w.y, acc[r][1]);
            acc[r][2] = fmaf(a, w.z, acc[r][2]);
            acc[r][3] = fmaf(a, w.w, acc[r][3]);
        }
    }
#pragma unroll
    for (int r = 0; r < 16; r++) {
        float4 o; o.x = acc[r][0]; o.y = acc[r][1]; o.z = acc[r][2]; o.w = acc[r][3];
        *(float4*)(g_xpe + (size_t)(row0 + r) * 512 + c0) = o;
    }
}

// ================= Kernel 2: fused skip-LSTM recurrence =================
__device__ __forceinline__ void lstm_step(
    int tid, int t, const float* xp, const float* __restrict__ rk,
    const float* __restrict__ k2w, const float* __restrict__ bias2,
    float s0, float* sg, float* sc, float* ph, float* spre, float* sh,
    float* out_h) {
    if (tid < 256) {
        const int j0 = tid * 2;
        const int q  = j0 >> 7;
        const float* w = rk + j0;
        const float* s = sg + (q << 7);
        float a0 = xp[j0], a1 = xp[j0 + 1];
#pragma unroll 4
        for (int k = 0; k < 128; k++) {
            float2 wv = *(const float2*)(w + k * 512);
            float sv = s[k];
            a0 = fmaf(sv, wv.x, a0);
            a1 = fmaf(sv, wv.y, a1);
        }
        spre[j0] = a0; spre[j0 + 1] = a1;
    } else {
        const int j0 = (tid - 256) * 2;
        const float* hold = ph + ((t & (SKIPN - 1)) << 7);
        float a0 = bias2[j0], a1 = bias2[j0 + 1];
#pragma unroll 4
        for (int k = 0; k < 128; k++) {
            float2 wv = *(const float2*)(k2w + k * 128 + j0);
            float sv = hold[k];
            a0 = fmaf(sv, wv.x, a0);
            a1 = fmaf(sv, wv.y, a1);
        }
        spre[512 + j0] = a0; spre[512 + j0 + 1] = a1;
    }
    __syncthreads();
    if (tid < 128) {
        const int j = tid;
        float gi = sigm(spre[j]);
        float gf = sigm(spre[128 + j]);
        float cb = tanhf(spre[256 + j]);
        float go = sigm(spre[384 + j]);
        float c  = gf * sc[j] + gi * cb;
        float hs = sigm(spre[512 + j]);
        float h  = s0 * (go * tanhf(c)) + (1.0f - s0) * hs;
        sg[j] = gi; sg[128 + j] = gf; sg[256 + j] = c; sg[384 + j] = go;
        sc[j] = c;
        ph[((t & (SKIPN - 1)) << 7) + j] = h;
        sh[j] = h;
        if (out_h) out_h[j] = h;
    }
    __syncthreads();
}

__global__ __launch_bounds__(320) void k_lstm(
    const float* __restrict__ enc_rk, const float* __restrict__ enc_k2,
    const float* __restrict__ enc_b2, const float* __restrict__ enc_s0p,
    const float* __restrict__ dec_k,  const float* __restrict__ dec_rk,
    const float* __restrict__ dec_k2, const float* __restrict__ dec_b,
    const float* __restrict__ dec_b2, const float* __restrict__ dec_s0p) {
    __shared__ __align__(16) float sg[512];
    __shared__ __align__(16) float sc[128];
    __shared__ __align__(16) float sh[128];
    __shared__ __align__(16) float ph[SKIPN * 128];
    __shared__ __align__(16) float spre[640];
    __shared__ __align__(16) float xpd[512];

    const int tid = threadIdx.x;
    const int b   = blockIdx.x;

    for (int i = tid; i < 512; i += 320) sg[i] = 0.f;
    for (int i = tid; i < 128; i += 320) sc[i] = 0.f;
    for (int i = tid; i < SKIPN * 128; i += 320) ph[i] = 0.f;
    __syncthreads();

    const float s0e = *enc_s0p;
    for (int t = 0; t < TSTEPS; t++) {
        const float* xp = g_xpe + ((size_t)t * 64 + b) * 512;
        lstm_step(tid, t, xp, enc_rk, enc_k2, enc_b2, s0e, sg, sc, ph, spre, sh, nullptr);
    }

    if (tid < 256) {
        const int j0 = tid * 2;
        float a0 = dec_b[j0], a1 = dec_b[j0 + 1];
#pragma unroll 4
        for (int k = 0; k < 128; k++) {
            float2 wv = *(const float2*)(dec_k + k * 512 + j0);
            float sv = sh[k];
            a0 = fmaf(sv, wv.x, a0);
            a1 = fmaf(sv, wv.y, a1);
        }
        xpd[j0] = a0; xpd[j0 + 1] = a1;
    }
    for (int i = tid; i < 512; i += 320) sg[i] = 0.f;
    for (int i = tid; i < 128; i += 320) sc[i] = 0.f;
    for (int i = tid; i < SKIPN * 128; i += 320) ph[i] = 0.f;
    __syncthreads();

    const float s0d = *dec_s0p;
    for (int t = 0; t < TSTEPS; t++) {
        lstm_step(tid, t, xpd, dec_rk, dec_k2, dec_b2, s0d, sg, sc, ph, spre, sh,
                  g_flat + (size_t)b * FLATN + t * 128);
    }
}

// ================= Kernel 3: dense layer via mma.sync tf32 =================
// Y[b, j] = dense_b[j] + sum_k flat[b,k] * W[j,k]
// M-dim = j (128/CTA), N-dim = b (64), K chunks of 32.
// 8 warps: warp_m = wid&3 (32 j each), warp_n = wid>>2 (32 b each).
// SMEM tiles [row][k] with row stride 36 floats (pad 4): conflict-free fragment lds.
#define DK_ROWSTRIDE 36
#define DK_ASTG      (128 * DK_ROWSTRIDE)          // floats
#define DK_BSTG      (64 * DK_ROWSTRIDE)
#define DK_STGF      (DK_ASTG + DK_BSTG)           // 6912 floats
#define DK_STAGES    4
#define DK_SMEM      (DK_STAGES * DK_STGF * 4)     // 110592 bytes

__device__ __forceinline__ void dk_load(uint32_t sb, int buf, int chunk,
                                        const float* __restrict__ W, int j0, int tid) {
    const int k0 = chunk * 32;
    const uint32_t stg = sb + (uint32_t)buf * (DK_STGF * 4);
    // A: W tile, 128 rows x 32 k. thread: row = tid>>1, 4 chunks of 16B
    {
        const int r = tid >> 1;
        const int h = (tid & 1) * 16;  // float offset
        const float* g = W + (size_t)(j0 + r) * FLATN + k0 + h;
        uint32_t d = stg + (uint32_t)r * (DK_ROWSTRIDE * 4) + h * 4;
#pragma unroll
        for (int i = 0; i < 4; i++) cp16(d + i * 16, g + i * 4);
    }
    // B: flat tile, 64 rows x 32 k. thread: row = tid&63, 2 chunks of 16B
    {
        const int r = tid & 63;
        const int h = (tid >> 6) * 8;  // float offset
        const float* g = g_flat + (size_t)r * FLATN + k0 + h;
        uint32_t d = stg + (uint32_t)(DK_ASTG * 4) + (uint32_t)r * (DK_ROWSTRIDE * 4) + h * 4;
#pragma unroll
        for (int i = 0; i < 2; i++) cp16(d + i * 16, g + i * 4);
    }
}

__global__ __launch_bounds__(256, 1) void k_dense_mma(const float* __restrict__ W,
                                                      const float* __restrict__ db,
                                                      float* __restrict__ out) {
    extern __shared__ __align__(16) float smem[];
    const uint32_t sb = smem_u32(smem);
    const int tid = threadIdx.x;
    const int wid = tid >> 5, lid = tid & 31;
    const int g = lid >> 2, tig = lid & 3;     // groupID, thread-in-group
    const int warp_m = wid & 3, warp_n = wid >> 2;
    const int j0 = blockIdx.x * 128;

    float acc[2][4][4];
#pragma unroll
    for (int mt = 0; mt < 2; mt++)
#pragma unroll
        for (int nt = 0; nt < 4; nt++)
#pragma unroll
            for (int r = 0; r < 4; r++) acc[mt][nt][r] = 0.f;

    // prologue: stages 0..2
#pragma unroll
    for (int s = 0; s < 3; s++) {
        dk_load(sb, s, s, W, j0, tid);
        asm volatile("cp.async.commit_group;" ::: "memory");
    }

    const int jwA = warp_m * 32 + g;       // A frag base row within tile
    const int bwB = warp_n * 32 + g;       // B frag base row within tile

    for (int c = 0; c < 512; c++) {
        asm volatile("cp.async.wait_group 2;" ::: "memory");
        __syncthreads();

        // prefetch chunk c+3 into ring slot (overlaps compute below)
        if (c + 3 < 512) dk_load(sb, (c + 3) & 3, c + 3, W, j0, tid);
        asm volatile("cp.async.commit_group;" ::: "memory");

        const float* As = smem + (c & 3) * DK_STGF;
        const float* Bs = As + DK_ASTG;
#pragma unroll
        for (int ks = 0; ks < 4; ks++) {
            const int kk = ks * 8 + tig;
            uint32_t a[2][4];
#pragma unroll
            for (int mt = 0; mt < 2; mt++) {
                const float* ar = As + (jwA + mt * 16) * DK_ROWSTRIDE + kk;
                a[mt][0] = f2tf32(ar[0]);
                a[mt][1] = f2tf32(ar[8 * DK_ROWSTRIDE]);
                a[mt][2] = f2tf32(ar[4]);
                a[mt][3] = f2tf32(ar[8 * DK_ROWSTRIDE + 4]);
            }
#pragma unroll
            for (int nt = 0; nt < 4; nt++) {
                const float* br = Bs + (bwB + nt * 8) * DK_ROWSTRIDE + kk;
                uint32_t b0 = f2tf32(br[0]);
                uint32_t b1 = f2tf32(br[4]);
                mma16n8k8(acc[0][nt], a[0], b0, b1);
                mma16n8k8(acc[1][nt], a[1], b0, b1);
            }
        }
    }

    // epilogue: out[b * FLATN + j] = acc + db[j]
#pragma unroll
    for (int mt = 0; mt < 2; mt++) {
        const int jr0 = j0 + warp_m * 32 + mt * 16 + g;
        const float bj0 = db[jr0];
        const float bj8 = db[jr0 + 8];
#pragma unroll
        for (int nt = 0; nt < 4; nt++) {
            const int bb = warp_n * 32 + nt * 8 + 2 * tig;
            out[(size_t)bb * FLATN + jr0]           = acc[mt][nt][0] + bj0;
            out[(size_t)(bb + 1) * FLATN + jr0]     = acc[mt][nt][1] + bj0;
            out[(size_t)bb * FLATN + jr0 + 8]       = acc[mt][nt][2] + bj8;
            out[(size_t)(bb + 1) * FLATN + jr0 + 8] = acc[mt][nt][3] + bj8;
        }
    }
}

// ================= launch =================
extern "C" void kernel_launch(void* const* d_in, const int* in_sizes, int n_in,
                              void* d_out, int out_size) {
    const float* X      = (const float*)d_in[0];
    const float* enc_k  = (const float*)d_in[1];
    const float* enc_rk = (const float*)d_in[2];
    const float* enc_k2 = (const float*)d_in[3];
    const float* enc_b  = (const float*)d_in[4];
    const float* enc_b2 = (const float*)d_in[5];
    const float* enc_s0 = (const float*)d_in[6];
    const float* dec_k  = (const float*)d_in[7];
    const float* dec_rk = (const float*)d_in[8];
    const float* dec_k2 = (const float*)d_in[9];
    const float* dec_b  = (const float*)d_in[10];
    const float* dec_b2 = (const float*)d_in[11];
    const float* dec_s0 = (const float*)d_in[12];
    const float* dw     = (const float*)d_in[13];
    const float* db     = (const float*)d_in[14];
    float* out = (float*)d_out;

    cudaFuncSetAttribute(k_dense_mma, cudaFuncAttributeMaxDynamicSharedMemorySize, DK_SMEM);

    k_xproj<<<512, 128>>>(X, enc_k, enc_b);
    k_lstm<<<64, 320>>>(enc_rk, enc_k2, enc_b2, enc_s0,
                        dec_k, dec_rk, dec_k2, dec_b, dec_b2, dec_s0);
    k_dense_mma<<<128, 256, DK_SMEM>>>(dw, db, out);
}

// round 11
// speedup vs baseline: 2.6634x; 2.1288x over previous
#include <cuda_runtime.h>
#include <cstdint>

#define U        128
#define G4       512
#define SKIPN    16
#define TSTEPS   128
#define BATCH    64
#define FLATN    16384   // SEQ * UNITS

// Scratch (device globals: allocation-free rule)
__device__ float g_xpe[8192 * 512];      // encoder input projections, row = t*64+b
__device__ float g_flat[BATCH * FLATN];  // decoder outputs (dense GEMM B-matrix)

__device__ __forceinline__ float sigm(float x) { return 1.0f / (1.0f + expf(-x)); }

__device__ __forceinline__ uint32_t smem_u32(const void* p) {
    uint32_t a;
    asm("{ .reg .u64 t; cvta.to.shared.u64 t, %1; cvt.u32.u64 %0, t; }" : "=r"(a) : "l"(p));
    return a;
}
__device__ __forceinline__ void cp16(uint32_t dst, const float* src) {
    asm volatile("cp.async.cg.shared.global [%0], [%1], 16;" :: "r"(dst), "l"(src));
}
__device__ __forceinline__ uint32_t f2tf32(float f) {
    uint32_t r;
    asm("cvt.rna.tf32.f32 %0, %1;" : "=r"(r) : "f"(f));
    return r;
}
__device__ __forceinline__ void mma16n8k8(float* c, const uint32_t* a, uint32_t b0, uint32_t b1) {
    asm volatile(
        "mma.sync.aligned.m16n8k8.row.col.f32.tf32.tf32.f32 "
        "{%0,%1,%2,%3}, {%4,%5,%6,%7}, {%8,%9}, {%0,%1,%2,%3};"
        : "+f"(c[0]), "+f"(c[1]), "+f"(c[2]), "+f"(c[3])
        : "r"(a[0]), "r"(a[1]), "r"(a[2]), "r"(a[3]), "r"(b0), "r"(b1));
}

// ================= Kernel 1: encoder input projection =================
__global__ __launch_bounds__(128) void k_xproj(const float* __restrict__ X,
                                               const float* __restrict__ Wk,
                                               const float* __restrict__ bias) {
    __shared__ float As[128 * 16];   // [k][r] transposed
    const int tid  = threadIdx.x;
    const int row0 = blockIdx.x * 16;

    for (int idx = tid; idx < 16 * 128; idx += 128) {
        int r = idx >> 7, m = idx & 127;
        int row = row0 + r;
        int t = row >> 6, b = row & 63;
        As[m * 16 + r] = X[(size_t)b * 32768 + t * 128 + m];
    }
    __syncthreads();

    const int c0 = tid * 4;
    float4 bs = *(const float4*)(bias + c0);
    float acc[16][4];
#pragma unroll
    for (int r = 0; r < 16; r++) { acc[r][0] = bs.x; acc[r][1] = bs.y; acc[r][2] = bs.z; acc[r][3] = bs.w; }

#pragma unroll 4
    for (int k = 0; k < 128; k++) {
        float4 w = *(const float4*)(Wk + k * 512 + c0);
#pragma unroll
        for (int r = 0; r < 16; r++) {
            float a = As[k * 16 + r];
            acc[r][0] = fmaf(a, w.x, acc[r][0]);
            acc[r][1] = fmaf(a, w.y, acc[r][1]);
            acc[r][2] = fmaf(a, w.z, acc[r][2]);
            acc[r][3] = fmaf(a, w.w, acc[r][3]);
        }
    }
#pragma unroll
    for (int r = 0; r < 16; r++) {
        float4 o; o.x = acc[r][0]; o.y = acc[r][1]; o.z = acc[r][2]; o.w = acc[r][3];
        *(float4*)(g_xpe + (size_t)(row0 + r) * 512 + c0) = o;
    }
}

// ================= Kernel 2: fused skip-LSTM, SMEM-resident weights =======
// SMEM layout (floats):
#define LSK        64     // rk k-range held in SMEM
#define WS_STRIDE  68     // 68*4B=272 (16B aligned); banks 4t+4i -> conflict-free
#define K2_STRIDE  132    // 132*4B=528; banks 4t+4i -> conflict-free
#define OFF_WS     0
#define OFF_K2S    (512 * WS_STRIDE)                 // 34816
#define OFF_SG     (OFF_K2S + 128 * K2_STRIDE)       // 51712
#define OFF_SC     (OFF_SG + 512)
#define OFF_SH     (OFF_SC + 128)
#define OFF_PH     (OFF_SH + 128)
#define OFF_SPRE   (OFF_PH + SKIPN * 128)
#define OFF_XPD    (OFF_SPRE + 640)
#define LS_SMEMF   (OFF_XPD + 512)
#define LS_SMEM    (LS_SMEMF * 4)                    // 222720 bytes

__device__ __forceinline__ void lstm_step2(
    int tid, int t, const float* xp, const float* __restrict__ rkg,
    const float* ws, const float* k2s, float b2a, float b2b, float s0,
    float* sg, float* sc, float* ph, float* spre, float* sh, float* out_h) {
    if (tid < 256) {
        const int c0 = tid, c1 = tid + 256;
        const float* w0 = ws + c0 * WS_STRIDE;
        const float* w1 = ws + c1 * WS_STRIDE;
        const float* sv0 = sg + ((c0 >> 7) << 7);
        const float* sv1 = sg + ((c1 >> 7) << 7);
        float a0 = xp[c0], a1 = xp[c1];
#pragma unroll
        for (int k = 0; k < LSK; k += 4) {
            float4 sA = *(const float4*)(sv0 + k);
            float4 wA = *(const float4*)(w0 + k);
            a0 = fmaf(sA.x, wA.x, a0); a0 = fmaf(sA.y, wA.y, a0);
            a0 = fmaf(sA.z, wA.z, a0); a0 = fmaf(sA.w, wA.w, a0);
            float4 sB = *(const float4*)(sv1 + k);
            float4 wB = *(const float4*)(w1 + k);
            a1 = fmaf(sB.x, wB.x, a1); a1 = fmaf(sB.y, wB.y, a1);
            a1 = fmaf(sB.z, wB.z, a1); a1 = fmaf(sB.w, wB.w, a1);
        }
#pragma unroll 4
        for (int k = LSK; k < 128; k += 4) {
            float4 sA = *(const float4*)(sv0 + k);
            float4 sB = *(const float4*)(sv1 + k);
            float w00 = rkg[(k + 0) * 512 + c0], w01 = rkg[(k + 1) * 512 + c0];
            float w02 = rkg[(k + 2) * 512 + c0], w03 = rkg[(k + 3) * 512 + c0];
            float w10 = rkg[(k + 0) * 512 + c1], w11 = rkg[(k + 1) * 512 + c1];
            float w12 = rkg[(k + 2) * 512 + c1], w13 = rkg[(k + 3) * 512 + c1];
            a0 = fmaf(sA.x, w00, a0); a0 = fmaf(sA.y, w01, a0);
            a0 = fmaf(sA.z, w02, a0); a0 = fmaf(sA.w, w03, a0);
            a1 = fmaf(sB.x, w10, a1); a1 = fmaf(sB.y, w11, a1);
            a1 = fmaf(sB.z, w12, a1); a1 = fmaf(sB.w, w13, a1);
        }
        spre[c0] = a0; spre[c1] = a1;
    } else {
        const int c0 = tid - 256, c1 = c0 + 64;
        const float* hold = ph + ((t & (SKIPN - 1)) << 7);
        const float* w0 = k2s + c0 * K2_STRIDE;
        const float* w1 = k2s + c1 * K2_STRIDE;
        float a0 = b2a, a1 = b2b;
#pragma unroll
        for (int k = 0; k < 128; k += 4) {
            float4 h4 = *(const float4*)(hold + k);
            float4 wA = *(const float4*)(w0 + k);
            float4 wB = *(const float4*)(w1 + k);
            a0 = fmaf(h4.x, wA.x, a0); a0 = fmaf(h4.y, wA.y, a0);
            a0 = fmaf(h4.z, wA.z, a0); a0 = fmaf(h4.w, wA.w, a0);
            a1 = fmaf(h4.x, wB.x, a1); a1 = fmaf(h4.y, wB.y, a1);
            a1 = fmaf(h4.z, wB.z, a1); a1 = fmaf(h4.w, wB.w, a1);
        }
        spre[512 + c0] = a0; spre[512 + c1] = a1;
    }
    __syncthreads();
    if (tid < 128) {
        const int j = tid;
        float gi = sigm(spre[j]);
        float gf = sigm(spre[128 + j]);
        float cb = tanhf(spre[256 + j]);
        float go = sigm(spre[384 + j]);
        float c  = gf * sc[j] + gi * cb;
        float hs = sigm(spre[512 + j]);
        float h  = s0 * (go * tanhf(c)) + (1.0f - s0) * hs;
        sg[j] = gi; sg[128 + j] = gf; sg[256 + j] = c; sg[384 + j] = go;
        sc[j] = c;
        ph[((t & (SKIPN - 1)) << 7) + j] = h;
        sh[j] = h;
        if (out_h) out_h[j] = h;
    }
    __syncthreads();
}

__device__ __forceinline__ void ls_fill_weights(int tid, float* ws, float* k2s,
                                                const float* __restrict__ rk,
                                                const float* __restrict__ k2) {
    for (int idx = tid; idx < 512 * LSK; idx += 320) {
        int k = idx >> 9, j = idx & 511;
        ws[j * WS_STRIDE + k] = rk[k * 512 + j];
    }
    for (int idx = tid; idx < 128 * 128; idx += 320) {
        int k = idx >> 7, j = idx & 127;
        k2s[j * K2_STRIDE + k] = k2[k * 128 + j];
    }
}

__global__ __launch_bounds__(320, 1) void k_lstm2(
    const float* __restrict__ enc_rk, const float* __restrict__ enc_k2,
    const float* __restrict__ enc_b2, const float* __restrict__ enc_s0p,
    const float* __restrict__ dec_k,  const float* __restrict__ dec_rk,
    const float* __restrict__ dec_k2, const float* __restrict__ dec_b,
    const float* __restrict__ dec_b2, const float* __restrict__ dec_s0p) {
    extern __shared__ __align__(16) float ls[];
    float* ws   = ls + OFF_WS;
    float* k2s  = ls + OFF_K2S;
    float* sg   = ls + OFF_SG;
    float* sc   = ls + OFF_SC;
    float* sh   = ls + OFF_SH;
    float* ph   = ls + OFF_PH;
    float* spre = ls + OFF_SPRE;
    float* xpd  = ls + OFF_XPD;

    const int tid = threadIdx.x;
    const int b   = blockIdx.x;

    // encoder weights -> SMEM; zero state
    ls_fill_weights(tid, ws, k2s, enc_rk, enc_k2);
    for (int i = tid; i < 512; i += 320) sg[i] = 0.f;
    for (int i = tid; i < 128; i += 320) sc[i] = 0.f;
    for (int i = tid; i < SKIPN * 128; i += 320) ph[i] = 0.f;
    float b2a = 0.f, b2b = 0.f;
    if (tid >= 256) { b2a = enc_b2[tid - 256]; b2b = enc_b2[tid - 192]; }
    __syncthreads();

    const float s0e = *enc_s0p;
    for (int t = 0; t < TSTEPS; t++) {
        const float* xp = g_xpe + ((size_t)t * 64 + b) * 512;
        lstm_step2(tid, t, xp, enc_rk, ws, k2s, b2a, b2b, s0e,
                   sg, sc, ph, spre, sh, nullptr);
    }

    // decoder constant input projection: xpd = dec_bias + RE @ dec_kernel
    if (tid < 256) {
        const int j0 = tid * 2;
        float a0 = dec_b[j0], a1 = dec_b[j0 + 1];
#pragma unroll 4
        for (int k = 0; k < 128; k++) {
            float2 wv = *(const float2*)(dec_k + k * 512 + j0);
            float sv = sh[k];
            a0 = fmaf(sv, wv.x, a0);
            a1 = fmaf(sv, wv.y, a1);
        }
        xpd[j0] = a0; xpd[j0 + 1] = a1;
    }
    // decoder weights -> SMEM; re-zero state (ws/sg/sc/ph untouched by xpd calc)
    ls_fill_weights(tid, ws, k2s, dec_rk, dec_k2);
    for (int i = tid; i < 512; i += 320) sg[i] = 0.f;
    for (int i = tid; i < 128; i += 320) sc[i] = 0.f;
    for (int i = tid; i < SKIPN * 128; i += 320) ph[i] = 0.f;
    if (tid >= 256) { b2a = dec_b2[tid - 256]; b2b = dec_b2[tid - 192]; }
    __syncthreads();

    const float s0d = *dec_s0p;
    for (int t = 0; t < TSTEPS; t++) {
        lstm_step2(tid, t, xpd, dec_rk, ws, k2s, b2a, b2b, s0d,
                   sg, sc, ph, spre, sh, g_flat + (size_t)b * FLATN + t * 128);
    }
}

// ================= Kernel 3: dense layer via mma.sync tf32 =================
#define DK_ROWSTRIDE 36
#define DK_ASTG      (128 * DK_ROWSTRIDE)
#define DK_BSTG      (64 * DK_ROWSTRIDE)
#define DK_STGF      (DK_ASTG + DK_BSTG)
#define DK_STAGES    4
#define DK_SMEM      (DK_STAGES * DK_STGF * 4)

__device__ __forceinline__ void dk_load(uint32_t sb, int buf, int chunk,
                                        const float* __restrict__ W, int j0, int tid) {
    const int k0 = chunk * 32;
    const uint32_t stg = sb + (uint32_t)buf * (DK_STGF * 4);
    {
        const int r = tid >> 1;
        const int h = (tid & 1) * 16;
        const float* g = W + (size_t)(j0 + r) * FLATN + k0 + h;
        uint32_t d = stg + (uint32_t)r * (DK_ROWSTRIDE * 4) + h * 4;
#pragma unroll
        for (int i = 0; i < 4; i++) cp16(d + i * 16, g + i * 4);
    }
    {
        const int r = tid & 63;
        const int h = (tid >> 6) * 8;
        const float* g = g_flat + (size_t)r * FLATN + k0 + h;
        uint32_t d = stg + (uint32_t)(DK_ASTG * 4) + (uint32_t)r * (DK_ROWSTRIDE * 4) + h * 4;
#pragma unroll
        for (int i = 0; i < 2; i++) cp16(d + i * 16, g + i * 4);
    }
}

__global__ __launch_bounds__(256, 1) void k_dense_mma(const float* __restrict__ W,
                                                      const float* __restrict__ db,
                                                      float* __restrict__ out) {
    extern __shared__ __align__(16) float smem[];
    const uint32_t sb = smem_u32(smem);
    const int tid = threadIdx.x;
    const int wid = tid >> 5, lid = tid & 31;
    const int g = lid >> 2, tig = lid & 3;
    const int warp_m = wid & 3, warp_n = wid >> 2;
    const int j0 = blockIdx.x * 128;

    float acc[2][4][4];
#pragma unroll
    for (int mt = 0; mt < 2; mt++)
#pragma unroll
        for (int nt = 0; nt < 4; nt++)
#pragma unroll
            for (int r = 0; r < 4; r++) acc[mt][nt][r] = 0.f;

#pragma unroll
    for (int s = 0; s < 3; s++) {
        dk_load(sb, s, s, W, j0, tid);
        asm volatile("cp.async.commit_group;" ::: "memory");
    }

    const int jwA = warp_m * 32 + g;
    const int bwB = warp_n * 32 + g;

    for (int c = 0; c < 512; c++) {
        asm volatile("cp.async.wait_group 2;" ::: "memory");
        __syncthreads();

        if (c + 3 < 512) dk_load(sb, (c + 3) & 3, c + 3, W, j0, tid);
        asm volatile("cp.async.commit_group;" ::: "memory");

        const float* As = smem + (c & 3) * DK_STGF;
        const float* Bs = As + DK_ASTG;
#pragma unroll
        for (int ks = 0; ks < 4; ks++) {
            const int kk = ks * 8 + tig;
            uint32_t a[2][4];
#pragma unroll
            for (int mt = 0; mt < 2; mt++) {
                const float* ar = As + (jwA + mt * 16) * DK_ROWSTRIDE + kk;
                a[mt][0] = f2tf32(ar[0]);
                a[mt][1] = f2tf32(ar[8 * DK_ROWSTRIDE]);
                a[mt][2] = f2tf32(ar[4]);
                a[mt][3] = f2tf32(ar[8 * DK_ROWSTRIDE + 4]);
            }
#pragma unroll
            for (int nt = 0; nt < 4; nt++) {
                const float* br = Bs + (bwB + nt * 8) * DK_ROWSTRIDE + kk;
                uint32_t b0 = f2tf32(br[0]);
                uint32_t b1 = f2tf32(br[4]);
                mma16n8k8(acc[0][nt], a[0], b0, b1);
                mma16n8k8(acc[1][nt], a[1], b0, b1);
            }
        }
    }

#pragma unroll
    for (int mt = 0; mt < 2; mt++) {
        const int jr0 = j0 + warp_m * 32 + mt * 16 + g;
        const float bj0 = db[jr0];
        const float bj8 = db[jr0 + 8];
#pragma unroll
        for (int nt = 0; nt < 4; nt++) {
            const int bb = warp_n * 32 + nt * 8 + 2 * tig;
            out[(size_t)bb * FLATN + jr0]           = acc[mt][nt][0] + bj0;
            out[(size_t)(bb + 1) * FLATN + jr0]     = acc[mt][nt][1] + bj0;
            out[(size_t)bb * FLATN + jr0 + 8]       = acc[mt][nt][2] + bj8;
            out[(size_t)(bb + 1) * FLATN + jr0 + 8] = acc[mt][nt][3] + bj8;
        }
    }
}

// ================= launch =================
extern "C" void kernel_launch(void* const* d_in, const int* in_sizes, int n_in,
                              void* d_out, int out_size) {
    const float* X      = (const float*)d_in[0];
    const float* enc_k  = (const float*)d_in[1];
    const float* enc_rk = (const float*)d_in[2];
    const float* enc_k2 = (const float*)d_in[3];
    const float* enc_b  = (const float*)d_in[4];
    const float* enc_b2 = (const float*)d_in[5];
    const float* enc_s0 = (const float*)d_in[6];
    const float* dec_k  = (const float*)d_in[7];
    const float* dec_rk = (const float*)d_in[8];
    const float* dec_k2 = (const float*)d_in[9];
    const float* dec_b  = (const float*)d_in[10];
    const float* dec_b2 = (const float*)d_in[11];
    const float* dec_s0 = (const float*)d_in[12];
    const float* dw     = (const float*)d_in[13];
    const float* db     = (const float*)d_in[14];
    float* out = (float*)d_out;

    cudaFuncSetAttribute(k_lstm2, cudaFuncAttributeMaxDynamicSharedMemorySize, LS_SMEM);
    cudaFuncSetAttribute(k_dense_mma, cudaFuncAttributeMaxDynamicSharedMemorySize, DK_SMEM);

    k_xproj<<<512, 128>>>(X, enc_k, enc_b);
    k_lstm2<<<64, 320, LS_SMEM>>>(enc_rk, enc_k2, enc_b2, enc_s0,
                                  dec_k, dec_rk, dec_k2, dec_b, dec_b2, dec_s0);
    k_dense_mma<<<128, 256, DK_SMEM>>>(dw, db, out);
}

// round 12
// speedup vs baseline: 3.3652x; 1.2635x over previous
#include <cuda_runtime.h>
#include <cstdint>

#define U        128
#define G4       512
#define SKIPN    16
#define TSTEPS   128
#define BATCH    64
#define FLATN    16384   // SEQ * UNITS

// Scratch (device globals: allocation-free rule)
__device__ float g_xpe[8192 * 512];      // encoder input projections, row = t*64+b
__device__ float g_flat[BATCH * FLATN];  // decoder outputs (dense GEMM B-matrix)

__device__ __forceinline__ float sigm(float x) { return 1.0f / (1.0f + expf(-x)); }

__device__ __forceinline__ uint32_t smem_u32(const void* p) {
    uint32_t a;
    asm("{ .reg .u64 t; cvta.to.shared.u64 t, %1; cvt.u32.u64 %0, t; }" : "=r"(a) : "l"(p));
    return a;
}
__device__ __forceinline__ void cp16(uint32_t dst, const float* src) {
    asm volatile("cp.async.cg.shared.global [%0], [%1], 16;" :: "r"(dst), "l"(src));
}
__device__ __forceinline__ uint32_t f2tf32(float f) {
    uint32_t r;
    asm("cvt.rna.tf32.f32 %0, %1;" : "=r"(r) : "f"(f));
    return r;
}
__device__ __forceinline__ void mma16n8k8(float* c, const uint32_t* a, uint32_t b0, uint32_t b1) {
    asm volatile(
        "mma.sync.aligned.m16n8k8.row.col.f32.tf32.tf32.f32 "
        "{%0,%1,%2,%3}, {%4,%5,%6,%7}, {%8,%9}, {%0,%1,%2,%3};"
        : "+f"(c[0]), "+f"(c[1]), "+f"(c[2]), "+f"(c[3])
        : "r"(a[0]), "r"(a[1]), "r"(a[2]), "r"(a[3]), "r"(b0), "r"(b1));
}
__device__ __forceinline__ uint32_t ctarank() {
    uint32_t r; asm("mov.u32 %0, %%cluster_ctarank;" : "=r"(r)); return r;
}
__device__ __forceinline__ uint32_t mapa_u32(uint32_t a, uint32_t rank) {
    uint32_t o; asm("mapa.shared::cluster.u32 %0, %1, %2;" : "=r"(o) : "r"(a), "r"(rank)); return o;
}
__device__ __forceinline__ void st_cluster_f32(uint32_t addr, float v) {
    asm volatile("st.shared::cluster.f32 [%0], %1;" :: "r"(addr), "f"(v) : "memory");
}
#define CLUSTER_SYNC() do { \
    asm volatile("barrier.cluster.arrive.aligned;" ::: "memory"); \
    asm volatile("barrier.cluster.wait.aligned;" ::: "memory"); \
} while (0)

// ================= Kernel 1: encoder input projection =================
__global__ __launch_bounds__(128) void k_xproj(const float* __restrict__ X,
                                               const float* __restrict__ Wk,
                                               const float* __restrict__ bias) {
    __shared__ float As[128 * 16];   // [k][r] transposed
    const int tid  = threadIdx.x;
    const int row0 = blockIdx.x * 16;

    for (int idx = tid; idx < 16 * 128; idx += 128) {
        int r = idx >> 7, m = idx & 127;
        int row = row0 + r;
        int t = row >> 6, b = row & 63;
        As[m * 16 + r] = X[(size_t)b * 32768 + t * 128 + m];
    }
    __syncthreads();

    const int c0 = tid * 4;
    float4 bs = *(const float4*)(bias + c0);
    float acc[16][4];
#pragma unroll
    for (int r = 0; r < 16; r++) { acc[r][0] = bs.x; acc[r][1] = bs.y; acc[r][2] = bs.z; acc[r][3] = bs.w; }

#pragma unroll 4
    for (int k = 0; k < 128; k++) {
        float4 w = *(const float4*)(Wk + k * 512 + c0);
#pragma unroll
        for (int r = 0; r < 16; r++) {
            float a = As[k * 16 + r];
            acc[r][0] = fmaf(a, w.x, acc[r][0]);
            acc[r][1] = fmaf(a, w.y, acc[r][1]);
            acc[r][2] = fmaf(a, w.z, acc[r][2]);
            acc[r][3] = fmaf(a, w.w, acc[r][3]);
        }
    }
#pragma unroll
    for (int r = 0; r < 16; r++) {
        float4 o; o.x = acc[r][0]; o.y = acc[r][1]; o.z = acc[r][2]; o.w = acc[r][3];
        *(float4*)(g_xpe + (size_t)(row0 + r) * 512 + c0) = o;
    }
}

// ============ Kernel 2: clustered skip-LSTM, all weights SMEM-resident ======
// Cluster of 2 CTAs per batch. CTA rank r owns gate columns [r*256, r*256+256)
// and skip columns [r*64, r*64+64). State (sg/sc/ph/sh) replicated in both CTAs
// via redundant elementwise; preactivations exchanged through DSMEM each step.
#define L3_WSTRIDE 132   // 132 mod 32 == 4 -> LDS.128 conflict-free
#define L3_OFF_WS   0
#define L3_OFF_K2   (256 * L3_WSTRIDE)               // 33792
#define L3_OFF_SG   (L3_OFF_K2 + 64 * L3_WSTRIDE)    // 42240
#define L3_OFF_SC   (L3_OFF_SG + 512)
#define L3_OFF_SH   (L3_OFF_SC + 128)
#define L3_OFF_PH   (L3_OFF_SH + 128)
#define L3_OFF_SPRE (L3_OFF_PH + SKIPN * 128)        // 2 parity buffers x 640
#define L3_OFF_XPD  (L3_OFF_SPRE + 1280)
#define L3_SMEMF    (L3_OFF_XPD + 256)
#define L3_SMEM     (L3_SMEMF * 4)                   // 186368 bytes

__device__ __forceinline__ void l3_fill(int tid, int rank, float* ws, float* k2s,
                                        const float* __restrict__ rk,
                                        const float* __restrict__ k2) {
    // ws[col][k] = rk[k][rank*256 + col]   (256 cols x 128 k)
    for (int idx = tid; idx < 256 * 128; idx += 320) {
        int col = idx & 255, k = idx >> 8;
        ws[col * L3_WSTRIDE + k] = rk[k * 512 + rank * 256 + col];
    }
    // k2s[col][k] = k2[k][rank*64 + col]   (64 cols x 128 k)
    for (int idx = tid; idx < 64 * 128; idx += 320) {
        int col = idx & 63, k = idx >> 6;
        k2s[col * L3_WSTRIDE + k] = k2[k * 128 + rank * 64 + col];
    }
}

__global__ __launch_bounds__(320, 1) __cluster_dims__(2, 1, 1)
void k_lstm3(
    const float* __restrict__ enc_rk, const float* __restrict__ enc_k2,
    const float* __restrict__ enc_b2, const float* __restrict__ enc_s0p,
    const float* __restrict__ dec_k,  const float* __restrict__ dec_rk,
    const float* __restrict__ dec_k2, const float* __restrict__ dec_b,
    const float* __restrict__ dec_b2, const float* __restrict__ dec_s0p) {
    extern __shared__ __align__(16) float ls[];
    float* ws   = ls + L3_OFF_WS;
    float* k2s  = ls + L3_OFF_K2;
    float* sg   = ls + L3_OFF_SG;
    float* sc   = ls + L3_OFF_SC;
    float* sh   = ls + L3_OFF_SH;
    float* ph   = ls + L3_OFF_PH;
    float* spre = ls + L3_OFF_SPRE;
    float* xpd  = ls + L3_OFF_XPD;

    const int tid  = threadIdx.x;
    const int rank = (int)ctarank();
    const int b    = blockIdx.x >> 1;
    const uint32_t sb = smem_u32(ls);
    const uint32_t rspre = mapa_u32(sb + L3_OFF_SPRE * 4, 1 - rank);

    // thread roles
    const int gcol = rank * 256 + tid;          // tid < 256: global gate column
    const int q    = gcol >> 7;                 // gate quadrant (uniform per warp)
    const int scl  = tid - 256;                 // tid >= 256: local skip column
    const int gs   = rank * 64 + scl;           // global skip column

    // ---------------- encoder setup ----------------
    l3_fill(tid, rank, ws, k2s, enc_rk, enc_k2);
    for (int i = tid; i < 512; i += 320) sg[i] = 0.f;
    for (int i = tid; i < 128; i += 320) sc[i] = 0.f;
    for (int i = tid; i < SKIPN * 128; i += 320) ph[i] = 0.f;
    float b2 = (tid >= 256) ? enc_b2[gs] : 0.f;
    const float s0e = *enc_s0p;
    const float s0d = *dec_s0p;
    __syncthreads();

    // ---------------- encoder loop ----------------
    for (int t = 0; t < TSTEPS; t++) {
        const int buf = (t & 1) * 640;
        if (tid < 256) {
            float a0 = g_xpe[((size_t)t * 64 + b) * 512 + gcol];
            float a1 = 0.f, a2 = 0.f, a3 = 0.f;
            const float* sv = sg + (q << 7);
            const float* w  = ws + tid * L3_WSTRIDE;
#pragma unroll 8
            for (int k = 0; k < 128; k += 4) {
                float4 s4 = *(const float4*)(sv + k);
                float4 w4 = *(const float4*)(w + k);
                a0 = fmaf(s4.x, w4.x, a0);
                a1 = fmaf(s4.y, w4.y, a1);
                a2 = fmaf(s4.z, w4.z, a2);
                a3 = fmaf(s4.w, w4.w, a3);
            }
            float acc = (a0 + a1) + (a2 + a3);
            const int si = buf + gcol;
            spre[si] = acc;
            st_cluster_f32(rspre + si * 4, acc);
        } else {
            float a0 = b2, a1 = 0.f, a2 = 0.f, a3 = 0.f;
            const float* hold = ph + ((t & (SKIPN - 1)) << 7);
            const float* w = k2s + scl * L3_WSTRIDE;
#pragma unroll 8
            for (int k = 0; k < 128; k += 4) {
                float4 h4 = *(const float4*)(hold + k);
                float4 w4 = *(const float4*)(w + k);
                a0 = fmaf(h4.x, w4.x, a0);
                a1 = fmaf(h4.y, w4.y, a1);
                a2 = fmaf(h4.z, w4.z, a2);
                a3 = fmaf(h4.w, w4.w, a3);
            }
            float acc = (a0 + a1) + (a2 + a3);
            const int si = buf + 512 + gs;
            spre[si] = acc;
            st_cluster_f32(rspre + si * 4, acc);
        }
        CLUSTER_SYNC();
        if (tid < 128) {
            const int j = tid;
            const float* sp = spre + buf;
            float gi = sigm(sp[j]);
            float gf = sigm(sp[128 + j]);
            float cb = tanhf(sp[256 + j]);
            float go = sigm(sp[384 + j]);
            float c  = gf * sc[j] + gi * cb;
            float hs = sigm(sp[512 + j]);
            float h  = s0e * (go * tanhf(c)) + (1.0f - s0e) * hs;
            sg[j] = gi; sg[128 + j] = gf; sg[256 + j] = c; sg[384 + j] = go;
            sc[j] = c;
            ph[((t & (SKIPN - 1)) << 7) + j] = h;
            sh[j] = h;
        }
        __syncthreads();
    }

    // ---------------- decoder setup ----------------
    // constant input projection for own columns: xpd[tid] = dec_b + RE @ dec_k
    if (tid < 256) {
        float a0 = dec_b[gcol], a1 = 0.f, a2 = 0.f, a3 = 0.f;
#pragma unroll 4
        for (int k = 0; k < 128; k += 4) {
            a0 = fmaf(sh[k + 0], dec_k[(k + 0) * 512 + gcol], a0);
            a1 = fmaf(sh[k + 1], dec_k[(k + 1) * 512 + gcol], a1);
            a2 = fmaf(sh[k + 2], dec_k[(k + 2) * 512 + gcol], a2);
            a3 = fmaf(sh[k + 3], dec_k[(k + 3) * 512 + gcol], a3);
        }
        xpd[tid] = (a0 + a1) + (a2 + a3);
    }
    __syncthreads();   // sh consumed before state re-zero
    l3_fill(tid, rank, ws, k2s, dec_rk, dec_k2);
    for (int i = tid; i < 512; i += 320) sg[i] = 0.f;
    for (int i = tid; i < 128; i += 320) sc[i] = 0.f;
    for (int i = tid; i < SKIPN * 128; i += 320) ph[i] = 0.f;
    if (tid >= 256) b2 = dec_b2[gs];
    __syncthreads();

    // ---------------- decoder loop ----------------
    for (int t = 0; t < TSTEPS; t++) {
        const int buf = (t & 1) * 640;
        if (tid < 256) {
            float a0 = xpd[tid];
            float a1 = 0.f, a2 = 0.f, a3 = 0.f;
            const float* sv = sg + (q << 7);
            const float* w  = ws + tid * L3_WSTRIDE;
#pragma unroll 8
            for (int k = 0; k < 128; k += 4) {
                float4 s4 = *(const float4*)(sv + k);
                float4 w4 = *(const float4*)(w + k);
                a0 = fmaf(s4.x, w4.x, a0);
                a1 = fmaf(s4.y, w4.y, a1);
                a2 = fmaf(s4.z, w4.z, a2);
                a3 = fmaf(s4.w, w4.w, a3);
            }
            float acc = (a0 + a1) + (a2 + a3);
            const int si = buf + gcol;
            spre[si] = acc;
            st_cluster_f32(rspre + si * 4, acc);
        } else {
            float a0 = b2, a1 = 0.f, a2 = 0.f, a3 = 0.f;
            const float* hold = ph + ((t & (SKIPN - 1)) << 7);
            const float* w = k2s + scl * L3_WSTRIDE;
#pragma unroll 8
            for (int k = 0; k < 128; k += 4) {
                float4 h4 = *(const float4*)(hold + k);
                float4 w4 = *(const float4*)(w + k);
                a0 = fmaf(h4.x, w4.x, a0);
                a1 = fmaf(h4.y, w4.y, a1);
                a2 = fmaf(h4.z, w4.z, a2);
                a3 = fmaf(h4.w, w4.w, a3);
            }
            float acc = (a0 + a1) + (a2 + a3);
            const int si = buf + 512 + gs;
            spre[si] = acc;
            st_cluster_f32(rspre + si * 4, acc);
        }
        CLUSTER_SYNC();
        if (tid < 128) {
            const int j = tid;
            const float* sp = spre + buf;
            float gi = sigm(sp[j]);
            float gf = sigm(sp[128 + j]);
            float cb = tanhf(sp[256 + j]);
            float go = sigm(sp[384 + j]);
            float c  = gf * sc[j] + gi * cb;
            float hs = sigm(sp[512 + j]);
            float h  = s0d * (go * tanhf(c)) + (1.0f - s0d) * hs;
            sg[j] = gi; sg[128 + j] = gf; sg[256 + j] = c; sg[384 + j] = go;
            sc[j] = c;
            ph[((t & (SKIPN - 1)) << 7) + j] = h;
            sh[j] = h;
            if (rank == 0) g_flat[(size_t)b * FLATN + t * 128 + j] = h;
        }
        __syncthreads();
    }
}

// ================= Kernel 3: dense layer via mma.sync tf32 =================
#define DK_ROWSTRIDE 36
#define DK_ASTG      (128 * DK_ROWSTRIDE)
#define DK_BSTG      (64 * DK_ROWSTRIDE)
#define DK_STGF      (DK_ASTG + DK_BSTG)
#define DK_STAGES    4
#define DK_SMEM      (DK_STAGES * DK_STGF * 4)

__device__ __forceinline__ void dk_load(uint32_t sb, int buf, int chunk,
                                        const float* __restrict__ W, int j0, int tid) {
    const int k0 = chunk * 32;
    const uint32_t stg = sb + (uint32_t)buf * (DK_STGF * 4);
    {
        const int r = tid >> 1;
        const int h = (tid & 1) * 16;
        const float* g = W + (size_t)(j0 + r) * FLATN + k0 + h;
        uint32_t d = stg + (uint32_t)r * (DK_ROWSTRIDE * 4) + h * 4;
#pragma unroll
        for (int i = 0; i < 4; i++) cp16(d + i * 16, g + i * 4);
    }
    {
        const int r = tid & 63;
        const int h = (tid >> 6) * 8;
        const float* g = g_flat + (size_t)r * FLATN + k0 + h;
        uint32_t d = stg + (uint32_t)(DK_ASTG * 4) + (uint32_t)r * (DK_ROWSTRIDE * 4) + h * 4;
#pragma unroll
        for (int i = 0; i < 2; i++) cp16(d + i * 16, g + i * 4);
    }
}

__global__ __launch_bounds__(256, 1) void k_dense_mma(const float* __restrict__ W,
                                                      const float* __restrict__ db,
                                                      float* __restrict__ out) {
    extern __shared__ __align__(16) float smem[];
    const uint32_t sb = smem_u32(smem);
    const int tid = threadIdx.x;
    const int wid = tid >> 5, lid = tid & 31;
    const int g = lid >> 2, tig = lid & 3;
    const int warp_m = wid & 3, warp_n = wid >> 2;
    const int j0 = blockIdx.x * 128;

    float acc[2][4][4];
#pragma unroll
    for (int mt = 0; mt < 2; mt++)
#pragma unroll
        for (int nt = 0; nt < 4; nt++)
#pragma unroll
            for (int r = 0; r < 4; r++) acc[mt][nt][r] = 0.f;

#pragma unroll
    for (int s = 0; s < 3; s++) {
        dk_load(sb, s, s, W, j0, tid);
        asm volatile("cp.async.commit_group;" ::: "memory");
    }

    const int jwA = warp_m * 32 + g;
    const int bwB = warp_n * 32 + g;

    for (int c = 0; c < 512; c++) {
        asm volatile("cp.async.wait_group 2;" ::: "memory");
        __syncthreads();

        if (c + 3 < 512) dk_load(sb, (c + 3) & 3, c + 3, W, j0, tid);
        asm volatile("cp.async.commit_group;" ::: "memory");

        const float* As = smem + (c & 3) * DK_STGF;
        const float* Bs = As + DK_ASTG;
#pragma unroll
        for (int ks = 0; ks < 4; ks++) {
            const int kk = ks * 8 + tig;
            uint32_t a[2][4];
#pragma unroll
            for (int mt = 0; mt < 2; mt++) {
                const float* ar = As + (jwA + mt * 16) * DK_ROWSTRIDE + kk;
                a[mt][0] = f2tf32(ar[0]);
                a[mt][1] = f2tf32(ar[8 * DK_ROWSTRIDE]);
                a[mt][2] = f2tf32(ar[4]);
                a[mt][3] = f2tf32(ar[8 * DK_ROWSTRIDE + 4]);
            }
#pragma unroll
            for (int nt = 0; nt < 4; nt++) {
                const float* br = Bs + (bwB + nt * 8) * DK_ROWSTRIDE + kk;
                uint32_t b0 = f2tf32(br[0]);
                uint32_t b1 = f2tf32(br[4]);
                mma16n8k8(acc[0][nt], a[0], b0, b1);
                mma16n8k8(acc[1][nt], a[1], b0, b1);
            }
        }
    }

#pragma unroll
    for (int mt = 0; mt < 2; mt++) {
        const int jr0 = j0 + warp_m * 32 + mt * 16 + g;
        const float bj0 = db[jr0];
        const float bj8 = db[jr0 + 8];
#pragma unroll
        for (int nt = 0; nt < 4; nt++) {
            const int bb = warp_n * 32 + nt * 8 + 2 * tig;
            out[(size_t)bb * FLATN + jr0]           = acc[mt][nt][0] + bj0;
            out[(size_t)(bb + 1) * FLATN + jr0]     = acc[mt][nt][1] + bj0;
            out[(size_t)bb * FLATN + jr0 + 8]       = acc[mt][nt][2] + bj8;
            out[(size_t)(bb + 1) * FLATN + jr0 + 8] = acc[mt][nt][3] + bj8;
        }
    }
}

// ================= launch =================
extern "C" void kernel_launch(void* const* d_in, const int* in_sizes, int n_in,
                              void* d_out, int out_size) {
    const float* X      = (const float*)d_in[0];
    const float* enc_k  = (const float*)d_in[1];
    const float* enc_rk = (const float*)d_in[2];
    const float* enc_k2 = (const float*)d_in[3];
    const float* enc_b  = (const float*)d_in[4];
    const float* enc_b2 = (const float*)d_in[5];
    const float* enc_s0 = (const float*)d_in[6];
    const float* dec_k  = (const float*)d_in[7];
    const float* dec_rk = (const float*)d_in[8];
    const float* dec_k2 = (const float*)d_in[9];
    const float* dec_b  = (const float*)d_in[10];
    const float* dec_b2 = (const float*)d_in[11];
    const float* dec_s0 = (const float*)d_in[12];
    const float* dw     = (const float*)d_in[13];
    const float* db     = (const float*)d_in[14];
    float* out = (float*)d_out;

    cudaFuncSetAttribute(k_lstm3, cudaFuncAttributeMaxDynamicSharedMemorySize, L3_SMEM);
    cudaFuncSetAttribute(k_dense_mma, cudaFuncAttributeMaxDynamicSharedMemorySize, DK_SMEM);

    k_xproj<<<512, 128>>>(X, enc_k, enc_b);
    k_lstm3<<<128, 320, L3_SMEM>>>(enc_rk, enc_k2, enc_b2, enc_s0,
                                   dec_k, dec_rk, dec_k2, dec_b, dec_b2, dec_s0);
    k_dense_mma<<<128, 256, DK_SMEM>>>(dw, db, out);
}